// round 1
// baseline (speedup 1.0000x reference)
#include <cuda_runtime.h>
#include <math.h>

// Problem shape (fixed by the dataset instance)
#define BATCH 16
#define HEADS 8
#define HDIM  128
#define BSIZE 16      // tokens per cache block
#define BPS   128     // blocks per sequence
#define TMAX  (BSIZE * BPS)   // 2048 tokens
#define THREADS 512
#define NWARPS  (THREADS / 32)    // 16
#define TPW     (TMAX / NWARPS)   // 128 tokens per warp

__device__ __forceinline__ float warp_sum(float v) {
#pragma unroll
    for (int o = 16; o > 0; o >>= 1) v += __shfl_xor_sync(0xffffffffu, v, o);
    return v;
}
__device__ __forceinline__ float warp_max(float v) {
#pragma unroll
    for (int o = 16; o > 0; o >>= 1) v = fmaxf(v, __shfl_xor_sync(0xffffffffu, v, o));
    return v;
}

__global__ __launch_bounds__(THREADS, 1)
void paged_attn_kernel(const float* __restrict__ q,
                       const float* __restrict__ knew,
                       const float* __restrict__ vnew,
                       const float* __restrict__ kcache,
                       const float* __restrict__ vcache,
                       const int*   __restrict__ block_tables,
                       const int*   __restrict__ context_lens,
                       float*       __restrict__ out)
{
    const float SCALE = 0.08838834764831845f;

    const int bh   = blockIdx.x;
    const int b    = bh / HEADS;
    const int h    = bh % HEADS;
    const int tid  = threadIdx.x;
    const int lane = tid & 31;
    const int w    = tid >> 5;

    __shared__ float s_scores[TMAX];
    __shared__ int   s_bt[BPS];
    __shared__ float s_red[NWARPS];
    __shared__ float s_acc[NWARPS][HDIM];
    __shared__ float s_bcast[2];

    if (tid < BPS) s_bt[tid] = block_tables[b * BPS + tid];

    const int ctx  = context_lens[b];
    const int last = ctx - 1;

    // q row (scaled), one float4 per lane covers all 128 dims across the warp
    float4 q4 = reinterpret_cast<const float4*>(q + (size_t)(b * HEADS + h) * HDIM)[lane];
    q4.x *= SCALE; q4.y *= SCALE; q4.z *= SCALE; q4.w *= SCALE;

    const float* kfresh = knew + (size_t)(b * HEADS + h) * HDIM;
    const float* vfresh = vnew + (size_t)(b * HEADS + h) * HDIM;

    __syncthreads();

    // ---------------- Phase 1: scores = (q . k_t) for this warp's tokens ----
    const int tbeg = w * TPW;
#pragma unroll 1
    for (int t0 = tbeg; t0 < tbeg + TPW; t0 += 4) {
        float4 kv[4];
#pragma unroll
        for (int i = 0; i < 4; i++) {
            const int t = t0 + i;
            const int blk = s_bt[t >> 4];            // t / BSIZE
            const size_t row = ((size_t)blk * BSIZE + (t & (BSIZE - 1))) * HEADS + h;
            const float* kr = (t == last) ? kfresh : (kcache + row * HDIM);
            kv[i] = reinterpret_cast<const float4*>(kr)[lane];
        }
#pragma unroll
        for (int i = 0; i < 4; i++) {
            float s = kv[i].x * q4.x + kv[i].y * q4.y + kv[i].z * q4.z + kv[i].w * q4.w;
            s = warp_sum(s);
            if (lane == i) {
                const int t = t0 + i;
                s_scores[t] = (t < ctx) ? s : -INFINITY;
            }
        }
    }
    __syncthreads();

    // ---------------- Phase 2: softmax over s_scores ------------------------
    float m = -INFINITY;
    for (int i = tid; i < TMAX; i += THREADS) m = fmaxf(m, s_scores[i]);
    m = warp_max(m);
    if (lane == 0) s_red[w] = m;
    __syncthreads();
    if (w == 0) {
        float mm = (lane < NWARPS) ? s_red[lane] : -INFINITY;
        mm = warp_max(mm);
        if (lane == 0) s_bcast[0] = mm;
    }
    __syncthreads();
    m = s_bcast[0];

    float psum = 0.f;
    for (int i = tid; i < TMAX; i += THREADS) {
        float e = __expf(s_scores[i] - m);   // exp(-inf) = 0 for masked tokens
        s_scores[i] = e;
        psum += e;
    }
    psum = warp_sum(psum);
    if (lane == 0) s_red[w] = psum;
    __syncthreads();
    if (w == 0) {
        float ss = (lane < NWARPS) ? s_red[lane] : 0.f;
        ss = warp_sum(ss);
        if (lane == 0) s_bcast[1] = ss;
    }
    __syncthreads();
    const float inv = 1.0f / s_bcast[1];

    // ---------------- Phase 3: out = sum_t p_t * v_t -----------------------
    float4 acc = make_float4(0.f, 0.f, 0.f, 0.f);
#pragma unroll 1
    for (int t0 = tbeg; t0 < tbeg + TPW; t0 += 4) {
        float4 vv[4];
        float  p[4];
#pragma unroll
        for (int i = 0; i < 4; i++) {
            const int t = t0 + i;
            const int blk = s_bt[t >> 4];
            const size_t row = ((size_t)blk * BSIZE + (t & (BSIZE - 1))) * HEADS + h;
            const float* vr = (t == last) ? vfresh : (vcache + row * HDIM);
            vv[i] = reinterpret_cast<const float4*>(vr)[lane];
            p[i]  = s_scores[t];
        }
#pragma unroll
        for (int i = 0; i < 4; i++) {
            acc.x += p[i] * vv[i].x;
            acc.y += p[i] * vv[i].y;
            acc.z += p[i] * vv[i].z;
            acc.w += p[i] * vv[i].w;
        }
    }
    reinterpret_cast<float4*>(s_acc[w])[lane] = acc;
    __syncthreads();

    if (tid < HDIM) {
        float r = 0.f;
#pragma unroll
        for (int ww = 0; ww < NWARPS; ww++) r += s_acc[ww][tid];
        out[(size_t)(b * HEADS + h) * HDIM + tid] = r * inv;
    }
}

extern "C" void kernel_launch(void* const* d_in, const int* in_sizes, int n_in,
                              void* d_out, int out_size)
{
    const float* q            = (const float*)d_in[0];
    const float* k            = (const float*)d_in[1];
    const float* v            = (const float*)d_in[2];
    const float* k_cache      = (const float*)d_in[3];
    const float* v_cache      = (const float*)d_in[4];
    // d_in[5] = slot_mapping (unused: substitution at t == ctx-1 is equivalent)
    const int*   block_tables = (const int*)d_in[6];
    const int*   context_lens = (const int*)d_in[7];
    float*       out          = (float*)d_out;

    paged_attn_kernel<<<BATCH * HEADS, THREADS>>>(
        q, k, v, k_cache, v_cache, block_tables, context_lens, out);
}

// round 2
// speedup vs baseline: 1.3125x; 1.3125x over previous
#include <cuda_runtime.h>
#include <math.h>

// Problem shape (fixed by the dataset instance)
#define BATCH 16
#define HEADS 8
#define HDIM  128
#define BSIZE 16               // tokens per cache block
#define BPS   128              // blocks per sequence
#define TMAX  (BSIZE * BPS)    // 2048 tokens
#define NSPLIT 4
#define TSPLIT (TMAX / NSPLIT) // 512 tokens per split
#define BLKSPLIT (TSPLIT / BSIZE) // 32 cache blocks per split
#define THREADS 256
#define NWARPS  (THREADS / 32)     // 8
#define TPW     (TSPLIT / NWARPS)  // 64 tokens per warp

// split-KV partial results (allocation-free scratch)
__device__ float g_part_o[BATCH * HEADS * NSPLIT * HDIM];
__device__ float g_part_m[BATCH * HEADS * NSPLIT];
__device__ float g_part_l[BATCH * HEADS * NSPLIT];

__device__ __forceinline__ float warp_sum(float v) {
#pragma unroll
    for (int o = 16; o > 0; o >>= 1) v += __shfl_xor_sync(0xffffffffu, v, o);
    return v;
}
__device__ __forceinline__ float warp_max(float v) {
#pragma unroll
    for (int o = 16; o > 0; o >>= 1) v = fmaxf(v, __shfl_xor_sync(0xffffffffu, v, o));
    return v;
}

__global__ __launch_bounds__(THREADS)
void paged_attn_split_kernel(const float* __restrict__ q,
                             const float* __restrict__ knew,
                             const float* __restrict__ vnew,
                             const float* __restrict__ kcache,
                             const float* __restrict__ vcache,
                             const int*   __restrict__ block_tables,
                             const int*   __restrict__ context_lens)
{
    const float SCALE = 0.08838834764831845f;

    const int bh    = blockIdx.x >> 2;          // / NSPLIT
    const int split = blockIdx.x & (NSPLIT - 1);
    const int b     = bh / HEADS;
    const int h     = bh % HEADS;
    const int tid   = threadIdx.x;
    const int lane  = tid & 31;
    const int w     = tid >> 5;
    const int tbase = split * TSPLIT;

    __shared__ float s_scores[TSPLIT];
    __shared__ int   s_bt[BLKSPLIT];
    __shared__ float s_red[NWARPS];
    __shared__ float s_acc[NWARPS][HDIM];
    __shared__ float s_bcast[2];

    if (tid < BLKSPLIT)
        s_bt[tid] = block_tables[b * BPS + split * BLKSPLIT + tid];

    const int ctx  = context_lens[b];
    const int last = ctx - 1;

    float4 q4 = reinterpret_cast<const float4*>(q + (size_t)(b * HEADS + h) * HDIM)[lane];
    q4.x *= SCALE; q4.y *= SCALE; q4.z *= SCALE; q4.w *= SCALE;

    const float* kfresh = knew + (size_t)(b * HEADS + h) * HDIM;
    const float* vfresh = vnew + (size_t)(b * HEADS + h) * HDIM;

    __syncthreads();

    // ------------- Phase 1: scores (8-deep load batches per warp) ----------
    const int lbeg = w * TPW;
#pragma unroll 1
    for (int l0 = lbeg; l0 < lbeg + TPW; l0 += 8) {
        float4 kv[8];
#pragma unroll
        for (int i = 0; i < 8; i++) {
            const int lt = l0 + i;                 // local token in split
            const int t  = tbase + lt;             // global token
            const int blk = s_bt[lt >> 4];
            const size_t row = ((size_t)blk * BSIZE + (t & (BSIZE - 1))) * HEADS + h;
            const float* kr = (t == last) ? kfresh : (kcache + row * HDIM);
            kv[i] = reinterpret_cast<const float4*>(kr)[lane];
        }
#pragma unroll
        for (int i = 0; i < 8; i++) {
            float s = kv[i].x * q4.x + kv[i].y * q4.y + kv[i].z * q4.z + kv[i].w * q4.w;
            s = warp_sum(s);
            if (lane == i) {
                const int lt = l0 + i;
                s_scores[lt] = (tbase + lt < ctx) ? s : -INFINITY;
            }
        }
    }
    __syncthreads();

    // ------------- Phase 2: local softmax (partial m, l) -------------------
    float m = -INFINITY;
    for (int i = tid; i < TSPLIT; i += THREADS) m = fmaxf(m, s_scores[i]);
    m = warp_max(m);
    if (lane == 0) s_red[w] = m;
    __syncthreads();
    if (w == 0) {
        float mm = (lane < NWARPS) ? s_red[lane] : -INFINITY;
        mm = warp_max(mm);
        if (lane == 0) s_bcast[0] = mm;
    }
    __syncthreads();
    m = s_bcast[0];
    const float msafe = (m == -INFINITY) ? 0.0f : m;  // avoid inf-inf = NaN

    float psum = 0.f;
    for (int i = tid; i < TSPLIT; i += THREADS) {
        float e = __expf(s_scores[i] - msafe);
        s_scores[i] = e;
        psum += e;
    }
    psum = warp_sum(psum);
    if (lane == 0) s_red[w] = psum;
    __syncthreads();
    if (w == 0) {
        float ss = (lane < NWARPS) ? s_red[lane] : 0.f;
        ss = warp_sum(ss);
        if (lane == 0) s_bcast[1] = ss;
    }

    // ------------- Phase 3: unnormalized o = sum p_t v_t -------------------
    float4 acc = make_float4(0.f, 0.f, 0.f, 0.f);
#pragma unroll 1
    for (int l0 = lbeg; l0 < lbeg + TPW; l0 += 8) {
        float4 vv[8];
        float  p[8];
#pragma unroll
        for (int i = 0; i < 8; i++) {
            const int lt = l0 + i;
            const int t  = tbase + lt;
            const int blk = s_bt[lt >> 4];
            const size_t row = ((size_t)blk * BSIZE + (t & (BSIZE - 1))) * HEADS + h;
            const float* vr = (t == last) ? vfresh : (vcache + row * HDIM);
            vv[i] = reinterpret_cast<const float4*>(vr)[lane];
            p[i]  = s_scores[lt];
        }
#pragma unroll
        for (int i = 0; i < 8; i++) {
            acc.x += p[i] * vv[i].x;
            acc.y += p[i] * vv[i].y;
            acc.z += p[i] * vv[i].z;
            acc.w += p[i] * vv[i].w;
        }
    }
    reinterpret_cast<float4*>(s_acc[w])[lane] = acc;
    __syncthreads();

    // ------------- write partials ------------------------------------------
    const int ps = bh * NSPLIT + split;
    if (tid < HDIM) {
        float r = 0.f;
#pragma unroll
        for (int ww = 0; ww < NWARPS; ww++) r += s_acc[ww][tid];
        g_part_o[(size_t)ps * HDIM + tid] = r;
    }
    if (tid == 0) {
        g_part_m[ps] = m;
        g_part_l[ps] = s_bcast[1];
    }
}

__global__ __launch_bounds__(HDIM)
void paged_attn_combine_kernel(float* __restrict__ out)
{
    const int bh  = blockIdx.x;
    const int tid = threadIdx.x;

    __shared__ float s_m[NSPLIT];
    __shared__ float s_l[NSPLIT];

    if (tid < NSPLIT) {
        s_m[tid] = g_part_m[bh * NSPLIT + tid];
        s_l[tid] = g_part_l[bh * NSPLIT + tid];
    }
    __syncthreads();

    float M = -INFINITY;
#pragma unroll
    for (int i = 0; i < NSPLIT; i++) M = fmaxf(M, s_m[i]);

    float coef[NSPLIT];
    float lsum = 0.f;
#pragma unroll
    for (int i = 0; i < NSPLIT; i++) {
        coef[i] = (s_m[i] == -INFINITY) ? 0.f : __expf(s_m[i] - M);
        lsum += coef[i] * s_l[i];
    }
    const float inv = 1.0f / lsum;

    float r = 0.f;
#pragma unroll
    for (int i = 0; i < NSPLIT; i++)
        r += coef[i] * g_part_o[((size_t)bh * NSPLIT + i) * HDIM + tid];

    out[(size_t)bh * HDIM + tid] = r * inv;
}

extern "C" void kernel_launch(void* const* d_in, const int* in_sizes, int n_in,
                              void* d_out, int out_size)
{
    const float* q            = (const float*)d_in[0];
    const float* k            = (const float*)d_in[1];
    const float* v            = (const float*)d_in[2];
    const float* k_cache      = (const float*)d_in[3];
    const float* v_cache      = (const float*)d_in[4];
    // d_in[5] = slot_mapping (unused: substitution at t == ctx-1 is equivalent)
    const int*   block_tables = (const int*)d_in[6];
    const int*   context_lens = (const int*)d_in[7];
    float*       out          = (float*)d_out;

    paged_attn_split_kernel<<<BATCH * HEADS * NSPLIT, THREADS>>>(
        q, k, v, k_cache, v_cache, block_tables, context_lens);
    paged_attn_combine_kernel<<<BATCH * HEADS, HDIM>>>(out);
}